// round 10
// baseline (speedup 1.0000x reference)
#include <cuda_runtime.h>
#include <cuda_fp16.h>
#include <math.h>

#define NA 4096
#define NB 4096
#define NS 4

typedef unsigned long long u64;

// Scratch (device globals — allocation-free per harness rules)
__device__ __half g_Kh [(size_t)NA * NB];   // K[n][m]  = exp(-C[n][m]/eps), fp16
__device__ __half g_KTh[(size_t)NB * NA];   // KT[m][n] = K[n][m], fp16
__device__ float  g_u  [NS * NA];           // u = exp(f/eps), s-major
__device__ float  g_v  [NS * NB];           // v = exp(g/eps), s-major

// ---------------------------------------------------------------------------
// f32x2 packed helpers (sm_103a FFMA2 path — only reachable via PTX)
// ---------------------------------------------------------------------------
__device__ __forceinline__ u64 pack_f32x2(float lo, float hi) {
    u64 r;
    asm("mov.b64 %0, {%1, %2};" : "=l"(r) : "f"(lo), "f"(hi));
    return r;
}
__device__ __forceinline__ void unpack_f32x2(u64 v, float& lo, float& hi) {
    asm("mov.b64 {%0, %1}, %2;" : "=f"(lo), "=f"(hi) : "l"(v));
}
__device__ __forceinline__ void fma_f32x2(u64& acc, u64 a, u64 b) {
    asm("fma.rn.f32x2 %0, %1, %2, %0;" : "+l"(acc) : "l"(a), "l"(b));
}
__device__ __forceinline__ u64 h2_to_f32x2(__half2 h) {
    const float2 f = __half22float2(h);
    return pack_f32x2(f.x, f.y);
}

// ---------------------------------------------------------------------------
// Kernel 1: K = exp(-C/eps) (fp16) and its transpose, tiled 32x32.
// ---------------------------------------------------------------------------
__global__ void expT_kernel(const float* __restrict__ C,
                            const float* __restrict__ eps_p) {
    __shared__ float tile[32][33];
    const float scale = -1.44269504088896340736f / eps_p[0];
    const int bx = blockIdx.x * 32, by = blockIdx.y * 32;
    const int tx = threadIdx.x, ty = threadIdx.y;             // (16, 16)

#pragma unroll
    for (int j = 0; j < 32; j += 16) {
        const int r = by + ty + j;
        const int c = bx + tx * 2;
        const float2 cv = *(const float2*)&C[(size_t)r * NB + c];
        const float e0 = exp2f(cv.x * scale);
        const float e1 = exp2f(cv.y * scale);
        *(__half2*)&g_Kh[(size_t)r * NB + c] = __floats2half2_rn(e0, e1);
        tile[ty + j][tx * 2]     = e0;
        tile[ty + j][tx * 2 + 1] = e1;
    }
    __syncthreads();
#pragma unroll
    for (int j = 0; j < 32; j += 16) {
        const int rr = ty + j;
        const int r  = bx + rr;
        const int c  = by + tx * 2;
        *(__half2*)&g_KTh[(size_t)r * NA + c] =
            __floats2half2_rn(tile[tx * 2][rr], tile[tx * 2 + 1][rr]);
    }
}

__global__ void init_v_kernel() {
    const int i = blockIdx.x * blockDim.x + threadIdx.x;
    if (i < NS * NB) g_v[i] = 1.0f;
}

// ---------------------------------------------------------------------------
// Kernel 3: one Sinkhorn half-step. K by direct LDG.128; x in fp16 smem;
// packed fma.rn.f32x2 accumulation over (even,odd) column pairs.
// 512 threads / 16 warps: each row-pair handled by TWO warps (column halves),
// partials combined via smem. 16 rows/block, grid 256 -> 4096 warps chip-wide.
//   dir=0: u = alpha / (K  v)    (x = v, scale 1)
//   dir=1: v = beta  / (KT u)    (x = u, scale 2^16 to keep fp16 normal)
// ---------------------------------------------------------------------------
__global__ void __launch_bounds__(512, 2) phase_kernel(const int dir,
                                                       const float* __restrict__ tgt) {
    __shared__ __half sx[NS * 4096];               // 32KB
    __shared__ float  sred[16][8];                 // per-warp partials
    const __half* __restrict__ M = dir ? g_KTh : g_Kh;
    const float*  __restrict__ x = dir ? g_u  : g_v;
    float*        __restrict__ out = dir ? g_v : g_u;
    const float sc = dir ? 65536.0f : 1.0f;

    const int tid = threadIdx.x;

    // Stage x (fp32 -> scaled fp16), float4 vectorized, 512 threads
    {
        const float4* __restrict__ x4 = (const float4*)x;
        __half2* s2 = (__half2*)sx;
#pragma unroll
        for (int i = tid; i < NS * 1024; i += 512) {
            const float4 v = x4[i];
            s2[i * 2]     = __floats2half2_rn(v.x * sc, v.y * sc);
            s2[i * 2 + 1] = __floats2half2_rn(v.z * sc, v.w * sc);
        }
    }
    __syncthreads();

    const int warp = tid >> 5;            // 0..15
    const int lane = tid & 31;
    const int p    = warp >> 1;           // row-pair 0..7
    const int h    = warp & 1;            // column half
    const int row0 = blockIdx.x * 16 + p * 2;

    const uint4* __restrict__ m0  = (const uint4*)(M + (size_t)row0 * 4096);
    const uint4* __restrict__ m1  = (const uint4*)(M + (size_t)(row0 + 1) * 4096);
    const uint4* __restrict__ sx4 = (const uint4*)sx;   // 8 halves per uint4

    u64 acc0[NS], acc1[NS];
    const u64 z = pack_f32x2(0.f, 0.f);
#pragma unroll
    for (int s = 0; s < NS; ++s) { acc0[s] = z; acc1[s] = z; }

    // This warp covers uint4 indices [h*256, h*256+256): 8 batches of 32,
    // front-batched 4 -> 8 LDG.128 in flight per step.
#pragma unroll
    for (int base = 0; base < 8; base += 4) {
        uint4 k0r[4], k1r[4];
#pragma unroll
        for (int j = 0; j < 4; ++j) {
            const int idx = h * 256 + (base + j) * 32 + lane;
            k0r[j] = m0[idx];
            k1r[j] = m1[idx];
        }
#pragma unroll
        for (int j = 0; j < 4; ++j) {
            const int idx = h * 256 + (base + j) * 32 + lane;
            u64 k0p[4], k1p[4];
#pragma unroll
            for (int q = 0; q < 4; ++q) {
                k0p[q] = h2_to_f32x2(((const __half2*)&k0r[j])[q]);
                k1p[q] = h2_to_f32x2(((const __half2*)&k1r[j])[q]);
            }
#pragma unroll
            for (int s = 0; s < NS; ++s) {
                const uint4 xv = sx4[s * 512 + idx];   // conflict-free LDS.128
#pragma unroll
                for (int q = 0; q < 4; ++q) {
                    const u64 xp = h2_to_f32x2(((const __half2*)&xv)[q]);
                    fma_f32x2(acc0[s], k0p[q], xp);
                    fma_f32x2(acc1[s], k1p[q], xp);
                }
            }
        }
    }

    // Collapse packed pairs, warp butterfly, publish per-warp partials
    float a0[NS], a1[NS];
#pragma unroll
    for (int s = 0; s < NS; ++s) {
        float lo, hi;
        unpack_f32x2(acc0[s], lo, hi);  a0[s] = lo + hi;
        unpack_f32x2(acc1[s], lo, hi);  a1[s] = lo + hi;
    }
#pragma unroll
    for (int s = 0; s < NS; ++s) {
#pragma unroll
        for (int o = 16; o > 0; o >>= 1) {
            a0[s] += __shfl_xor_sync(0xFFFFFFFFu, a0[s], o);
            a1[s] += __shfl_xor_sync(0xFFFFFFFFu, a1[s], o);
        }
    }
    if (lane == 0) {
#pragma unroll
        for (int s = 0; s < NS; ++s) {
            sred[warp][s]     = a0[s];
            sred[warp][4 + s] = a1[s];
        }
    }
    __syncthreads();

    // Combine column halves: 64 threads, one output each (8 pairs x 8 values)
    if (tid < 64) {
        const int p2 = tid >> 3;          // row-pair
        const int k  = tid & 7;           // r*4 + s
        const int s  = k & 3;
        const int r  = k >> 2;
        const float sum = sred[p2 * 2][k] + sred[p2 * 2 + 1][k];
        const int row = blockIdx.x * 16 + p2 * 2 + r;
        out[s * 4096 + row] = tgt[s * 4096 + row] * sc / sum;
    }
}

// ---------------------------------------------------------------------------
// Kernel 4: f = eps*log(u), g = eps*log(v)
// ---------------------------------------------------------------------------
__global__ void finalize_kernel(const float* __restrict__ eps_p,
                                float* __restrict__ out) {
    const int i = blockIdx.x * blockDim.x + threadIdx.x;
    const float eps = eps_p[0];
    if (i < NS * NA) {
        out[i]           = eps * logf(g_u[i]);
        out[i + NS * NA] = eps * logf(g_v[i]);
    }
}

// ---------------------------------------------------------------------------
extern "C" void kernel_launch(void* const* d_in, const int* in_sizes, int n_in,
                              void* d_out, int out_size) {
    const float* alpha = (const float*)d_in[0];   // (4, 4096)
    const float* beta  = (const float*)d_in[1];   // (4, 4096)
    const float* C     = (const float*)d_in[2];   // (4096, 4096)
    const float* eps   = (const float*)d_in[3];   // scalar
    float* out = (float*)d_out;                   // f (4,4096) then g (4,4096)

    expT_kernel<<<dim3(NB / 32, NA / 32), dim3(16, 16)>>>(C, eps);
    init_v_kernel<<<(NS * NB + 1023) / 1024, 1024>>>();

    for (int it = 0; it < 10; ++it) {
        phase_kernel<<<256, 512>>>(0, alpha);  // u = alpha/(K v)
        phase_kernel<<<256, 512>>>(1, beta);   // v = beta /(KT u)
    }

    finalize_kernel<<<(NS * NA + 255) / 256, 256>>>(eps, out);
}